// round 17
// baseline (speedup 1.0000x reference)
#include <cuda_runtime.h>

#define NB      32768
#define SLOTS   8
#define GRID    256

__device__ float g_Q1[64 * 64];
__device__ float g_E1[64 * 64];
__device__ unsigned int g_rk[64];
__device__ unsigned int g_bar;    // arrive counter (returns to 0 every run)

typedef unsigned long long u64;
typedef unsigned int u32;

__device__ u64 g_Bh[1024];
__device__ u64 g_Bl[1024];

#define ADD2T(d, x, y)     asm("add.rn.f32x2 %0, %1, %2;" : "=l"(d) : "l"(x), "l"(y))
#define UNPACK2(lo, hi, s) asm("mov.b64 {%0, %1}, %2;" : "=f"(lo), "=f"(hi) : "l"(s))
#define CVTP(d, fhi, flo)  asm("cvt.rn.bf16x2.f32 %0, %1, %2;" : "=r"(d) : "f"(fhi), "f"(flo))
#define MMA4(d0,d1,d2,d3,a0,a1,a2,a3,b0,b1) \
    asm("mma.sync.aligned.m16n8k16.row.col.f32.bf16.bf16.f32 " \
        "{%0,%1,%2,%3},{%4,%5,%6,%7},{%8,%9},{%0,%1,%2,%3};" \
        : "+f"(d0),"+f"(d1),"+f"(d2),"+f"(d3) \
        : "r"(a0),"r"(a1),"r"(a2),"r"(a3),"r"(b0),"r"(b1))

// smem layout (bytes) — r11 main layout; prep reuses [0, 16.5KB) as scratch
#define OFF_E1   0          // float[64*68]  = 17408
#define OFF_AHI  17408      // u32[128*36]   = 18432
#define OFF_ALO  35840      // u32[128*36]   = 18432
#define OFF_BH   54272      // u64[1024]     = 8192
#define OFF_BL   62464      // u64[1024]     = 8192
#define OFF_B2   70656      // float[64]
#define OFF_TOK  70912      // u64[128]
#define OFF_Q    71936      // int[128]
#define OFF_RK   72448      // u32[64]
#define SMEM_TOTAL 72704

static __device__ __forceinline__ void split_pack(
    float f00, float f01, float f10, float f11, u64* ph, u64* pl)
{
    u32 b0h, b1h, b0l, b1l;
    CVTP(b0h, f01, f00);
    CVTP(b1h, f11, f10);
    const float h00 = __uint_as_float(b0h << 16), h01 = __uint_as_float(b0h & 0xFFFF0000u);
    const float h10 = __uint_as_float(b1h << 16), h11 = __uint_as_float(b1h & 0xFFFF0000u);
    CVTP(b0l, f01 - h01, f00 - h00);
    CVTP(b1l, f11 - h11, f10 - h10);
    *ph = (u64)b0h | ((u64)b1h << 32);
    *pl = (u64)b0l | ((u64)b1l << 32);
}

// ---------------------------------------------------------------------------
// fused_k: 256 CTAs x 256 threads (2/SM, all co-resident).
//  PREP: CTA<64 tables | CTA 64-71 B2 frags | CTA 72 scores+ranks
//  device-wide arrive barrier (sense restored for graph replay)
//  MAIN: r11-proven scan||stage -> gather -> mma GEMM
// ---------------------------------------------------------------------------
__global__ void __launch_bounds__(256, 2) fused_k(
    const int*   __restrict__ seqs,
    const int*   __restrict__ qtok,
    const float* __restrict__ emb,
    const float* __restrict__ sw1, const float* __restrict__ sb1,
    const float* __restrict__ sw2, const float* __restrict__ sb2,
    const float* __restrict__ w1,  const float* __restrict__ b1,
    const float* __restrict__ w2,  const float* __restrict__ b2,
    float*       __restrict__ out)
{
    extern __shared__ __align__(16) char dyn[];
    const int tid = threadIdx.x;
    const int cta = blockIdx.x;

    // ================= PREP phase =================
    if (cta < 64) {
        float* s_e = (float*)dyn;
        if (tid < 16) ((float4*)s_e)[tid] = ((const float4*)(emb + cta * 64))[tid];
        __syncthreads();
        if (tid < 128) {
            const int half = tid >> 6;
            const int o    = tid & 63;
            const float* wcol = w1 + half * 64 * 64 + o;
            float acc = half ? 0.0f : b1[o];
#pragma unroll
            for (int k = 0; k < 64; k++) acc = fmaf(s_e[k], wcol[k * 64], acc);
            if (half) g_E1[cta * 64 + o] = acc * 0.125f;
            else      g_Q1[cta * 64 + o] = acc;
        }
    } else if (cta < 72) {
        if (tid < 128) {
            const int e = (cta - 64) * 128 + tid;
            const int tile = e >> 5, l = e & 31;
            const int kt = tile >> 3, nt = tile & 7;
            const int k0 = kt * 16 + (l & 3) * 2;
            const int n  = nt * 8 + (l >> 2);
            split_pack(w2[k0 * 64 + n], w2[(k0 + 1) * 64 + n],
                       w2[(k0 + 8) * 64 + n], w2[(k0 + 9) * 64 + n],
                       &g_Bh[e], &g_Bl[e]);
        }
    } else if (cta == 72) {
        float* sbuf = (float*)dyn;                    // 16KB emb copy
        float* s_s  = (float*)(dyn + 16384);          // 64 scores
#pragma unroll
        for (int i = tid; i < 1024; i += 256)
            ((float4*)sbuf)[i] = ((const float4*)emb)[i];
        __syncthreads();
        {
            const int tok = tid >> 2, p = tid & 3;
            float acc[8];
#pragma unroll
            for (int h = 0; h < 8; h++) acc[h] = sb1[p * 8 + h];
#pragma unroll 4
            for (int d = 0; d < 64; d++) {
                const float e = sbuf[tok * 64 + d];
                const float4 wa = *(const float4*)(sw1 + d * 32 + p * 8);
                const float4 wb = *(const float4*)(sw1 + d * 32 + p * 8 + 4);
                acc[0] = fmaf(e, wa.x, acc[0]); acc[1] = fmaf(e, wa.y, acc[1]);
                acc[2] = fmaf(e, wa.z, acc[2]); acc[3] = fmaf(e, wa.w, acc[3]);
                acc[4] = fmaf(e, wb.x, acc[4]); acc[5] = fmaf(e, wb.y, acc[5]);
                acc[6] = fmaf(e, wb.z, acc[6]); acc[7] = fmaf(e, wb.w, acc[7]);
            }
            float s = 0.f;
#pragma unroll
            for (int h = 0; h < 8; h++) s += fmaxf(acc[h], 0.f) * sw2[p * 8 + h];
            s += __shfl_down_sync(0xffffffffu, s, 2, 4);
            s += __shfl_down_sync(0xffffffffu, s, 1, 4);
            if (p == 0) s_s[tok] = s + sb2[0];
        }
        __syncthreads();
        if (tid < 64) {
            const float st = s_s[tid];
            int r = 0;
#pragma unroll 16
            for (int u = 0; u < 64; u++) r += (s_s[u] < st);
            g_rk[tid] = ((u32)r << 11) | (u32)tid;
        }
    }

    // ================= device-wide barrier =================
    __syncthreads();
    __threadfence();
    if (tid == 0) {
        atomicAdd(&g_bar, 1u);
        while (*(volatile u32*)&g_bar < (u32)GRID) __nanosleep(64);
        __threadfence();
    }
    __syncthreads();

    // ================= MAIN phase (r11 verbatim, rank pre-done) =================
    float* s_E1  = (float*)(dyn + OFF_E1);
    u64*   s_Ahi = (u64*)(dyn + OFF_AHI);
    u64*   s_Alo = (u64*)(dyn + OFF_ALO);
    u64*   s_Bh  = (u64*)(dyn + OFF_BH);
    u64*   s_Bl  = (u64*)(dyn + OFF_BL);
    float* s_b2  = (float*)(dyn + OFF_B2);
    u64*   s_tok = (u64*)(dyn + OFF_TOK);
    int*   s_q   = (int*)(dyn + OFF_Q);
    u32*   s_rk  = (u32*)(dyn + OFF_RK);

    if (tid < 64) { s_rk[tid] = g_rk[tid]; s_b2[tid] = b2[tid]; }
    __syncthreads();

    if (tid < 128) {
        // ---- eviction scan (integer keys) ----
        const int item = cta * 128 + tid;
        const int4* sp = (const int4*)seqs + item * 8;
        u32 w8[8];
#pragma unroll
        for (int g = 0; g < 8; g++) {
            const int4 v = sp[g];
            w8[g] = (u32)(v.x & 63) | ((u32)(v.y & 63) << 8) |
                    ((u32)(v.z & 63) << 16) | ((u32)(v.w & 63) << 24);
        }
        u32 k31[31];
#pragma unroll
        for (int j = 0; j < 31; j++) {
            const u32 t = (w8[j >> 2] >> ((j & 3) * 8)) & 63u;
            k31[j] = s_rk[t] + ((u32)j << 6);
        }
        u32 key[SLOTS];
#pragma unroll
        for (int j = 0; j < SLOTS; j++) key[j] = k31[j];
#pragma unroll
        for (int step = 8; step < 31; step++) {
            const u32 m01 = umin(key[0], key[1]);
            const u32 m23 = umin(key[2], key[3]);
            const u32 m45 = umin(key[4], key[5]);
            const u32 m67 = umin(key[6], key[7]);
            const u32 mk  = umin(umin(m01, m23), umin(m45, m67));
            const u32 nk  = k31[step];
#pragma unroll
            for (int j = 0; j < SLOTS; j++)
                key[j] = (key[j] == mk) ? nk : key[j];
        }
        u64 t8 = 0;
#pragma unroll
        for (int s = 0; s < SLOTS; s++) t8 |= (u64)(key[s] & 63u) << (8 * s);
        s_tok[tid] = t8;
        s_q[tid]   = qtok[item] & 63;
    } else {
        // ---- staging: E1 + B fragments ----
        const int t2 = tid - 128;
#pragma unroll
        for (int i4 = t2; i4 < 1024; i4 += 128) {
            const float4 e = ((const float4*)g_E1)[i4];
            *(float4*)(s_E1 + (i4 >> 4) * 68 + (i4 & 15) * 4) = e;
        }
#pragma unroll
        for (int i = t2; i < 512; i += 128) {
            ((ulonglong2*)s_Bh)[i] = ((const ulonglong2*)g_Bh)[i];
            ((ulonglong2*)s_Bl)[i] = ((const ulonglong2*)g_Bl)[i];
        }
    }
    __syncthreads();

    // ---- gather: layer1 tree-adds -> bf16 hi/lo A fragments ----
    {
        const int lane = tid & 31;
        const int wrp  = tid >> 5;
        const int o4   = lane & 15;
        const int hi16 = lane >> 4;
        const ulonglong2* E1q = (const ulonglong2*)s_E1;
        const ulonglong2* Q1q = (const ulonglong2*)g_Q1;
#pragma unroll
        for (int p = 0; p < 8; p++) {
            const int it = wrp * 16 + 2 * p + hi16;
            const u64 t8 = s_tok[it];
            const int q  = s_q[it];
            const ulonglong2 qv = Q1q[q * 16 + o4];
            ulonglong2 ev[SLOTS];
#pragma unroll
            for (int s = 0; s < SLOTS; s++)
                ev[s] = E1q[((int)((t8 >> (8 * s)) & 63)) * 17 + o4];
            u64 x0, x1, x2, x3, y0, y1, z0, P0, P1;
            ADD2T(x0, ev[0].x, ev[1].x); ADD2T(x1, ev[2].x, ev[3].x);
            ADD2T(x2, ev[4].x, ev[5].x); ADD2T(x3, ev[6].x, ev[7].x);
            ADD2T(y0, x0, x1); ADD2T(y1, x2, x3);
            ADD2T(z0, y0, y1); ADD2T(P0, z0, qv.x);
            ADD2T(x0, ev[0].y, ev[1].y); ADD2T(x1, ev[2].y, ev[3].y);
            ADD2T(x2, ev[4].y, ev[5].y); ADD2T(x3, ev[6].y, ev[7].y);
            ADD2T(y0, x0, x1); ADD2T(y1, x2, x3);
            ADD2T(z0, y0, y1); ADD2T(P1, z0, qv.y);

            float f0, f1, f2, f3;
            UNPACK2(f0, f1, P0); UNPACK2(f2, f3, P1);
            f0 = fmaxf(f0, 0.0f); f1 = fmaxf(f1, 0.0f);
            f2 = fmaxf(f2, 0.0f); f3 = fmaxf(f3, 0.0f);
            u32 h0, h1, l0, l1;
            CVTP(h0, f1, f0);
            CVTP(h1, f3, f2);
            const float hf0 = __uint_as_float(h0 << 16), hf1 = __uint_as_float(h0 & 0xFFFF0000u);
            const float hf2 = __uint_as_float(h1 << 16), hf3 = __uint_as_float(h1 & 0xFFFF0000u);
            CVTP(l0, f1 - hf1, f0 - hf0);
            CVTP(l1, f3 - hf3, f2 - hf2);
            s_Ahi[it * 18 + o4] = (u64)h0 | ((u64)h1 << 32);
            s_Alo[it * 18 + o4] = (u64)l0 | ((u64)l1 << 32);
        }
    }
    __syncthreads();

    // ---- layer2: mma.sync bf16 3-term GEMM ----
    {
        const int lane = tid & 31;
        const int mb   = tid >> 5;
        const int r0   = mb * 16 + (lane >> 2);
        const u32* Ah = (const u32*)s_Ahi;
        const u32* Al = (const u32*)s_Alo;

        u32 ah[16], al[16];
#pragma unroll
        for (int kt = 0; kt < 4; kt++) {
            const int kp = kt * 8 + (lane & 3);
            ah[4 * kt + 0] = Ah[r0 * 36 + kp];
            ah[4 * kt + 1] = Ah[(r0 + 8) * 36 + kp];
            ah[4 * kt + 2] = Ah[r0 * 36 + kp + 4];
            ah[4 * kt + 3] = Ah[(r0 + 8) * 36 + kp + 4];
            al[4 * kt + 0] = Al[r0 * 36 + kp];
            al[4 * kt + 1] = Al[(r0 + 8) * 36 + kp];
            al[4 * kt + 2] = Al[r0 * 36 + kp + 4];
            al[4 * kt + 3] = Al[(r0 + 8) * 36 + kp + 4];
        }

        const int item0 = cta * 128 + r0;
#pragma unroll
        for (int nt = 0; nt < 8; nt++) {
            float d0 = 0.f, d1 = 0.f, d2 = 0.f, d3 = 0.f;
#pragma unroll
            for (int kt = 0; kt < 4; kt++) {
                const u64 bh = s_Bh[(kt * 8 + nt) * 32 + lane];
                const u64 bl = s_Bl[(kt * 8 + nt) * 32 + lane];
                const u32 bh0 = (u32)bh, bh1 = (u32)(bh >> 32);
                const u32 bl0 = (u32)bl, bl1 = (u32)(bl >> 32);
                MMA4(d0,d1,d2,d3, ah[4*kt],ah[4*kt+1],ah[4*kt+2],ah[4*kt+3], bh0,bh1);
                MMA4(d0,d1,d2,d3, ah[4*kt],ah[4*kt+1],ah[4*kt+2],ah[4*kt+3], bl0,bl1);
                MMA4(d0,d1,d2,d3, al[4*kt],al[4*kt+1],al[4*kt+2],al[4*kt+3], bh0,bh1);
            }
            const int c0 = nt * 8 + (lane & 3) * 2;
            const float bb0 = s_b2[c0], bb1 = s_b2[c0 + 1];
            *(float2*)(out + (size_t)item0 * 64 + c0)       = make_float2(d0 + bb0, d1 + bb1);
            *(float2*)(out + (size_t)(item0 + 8) * 64 + c0) = make_float2(d2 + bb0, d3 + bb1);
        }
    }

    // ---- restore barrier sense for next graph replay ----
    __syncthreads();
    if (tid == 0) {
        const u32 v = atomicAdd(&g_bar, 1u);
        if (v == 2u * GRID - 1u) atomicExch(&g_bar, 0u);
    }
}

// ---------------------------------------------------------------------------
extern "C" void kernel_launch(void* const* d_in, const int* in_sizes, int n_in,
                              void* d_out, int out_size)
{
    const int*   seqs = (const int*)  d_in[0];
    const int*   qtok = (const int*)  d_in[1];
    const float* emb  = (const float*)d_in[2];
    const float* sw1  = (const float*)d_in[3];
    const float* sb1  = (const float*)d_in[4];
    const float* sw2  = (const float*)d_in[5];
    const float* sb2  = (const float*)d_in[6];
    const float* w1   = (const float*)d_in[7];
    const float* b1   = (const float*)d_in[8];
    const float* w2   = (const float*)d_in[9];
    const float* b2   = (const float*)d_in[10];
    float* out = (float*)d_out;

    cudaFuncSetAttribute(fused_k, cudaFuncAttributeMaxDynamicSharedMemorySize, SMEM_TOTAL);

    fused_k<<<GRID, 256, SMEM_TOTAL>>>(seqs, qtok, emb, sw1, sb1, sw2, sb2,
                                       w1, b1, w2, b2, out);
}